// round 16
// baseline (speedup 1.0000x reference)
#include <cuda_runtime.h>
#include <cuda_fp16.h>
#include <cuda_bf16.h>
#include <math.h>
#include <stdint.h>

#define Lc 6
#define Bc 16
#define Tc 512
#define Dc 512
#define Hc 8
#define Ac 64
#define Fc 2048
#define Ec 200000
#define BIASDIM 4

typedef __half fp16;
typedef __nv_bfloat16 bf16;

// ======================= helpers =============================================
__device__ __forceinline__ uint32_t smem_u32(const void* p) {
    uint32_t a;
    asm("{ .reg .u64 t; cvta.to.shared.u64 t, %1; cvt.u32.u64 %0, t; }"
        : "=r"(a) : "l"(p));
    return a;
}
__device__ __forceinline__ void cp16(uint32_t s, const void* g) {
    asm volatile("cp.async.cg.shared.global [%0], [%1], 16;" :: "r"(s), "l"(g));
}
__device__ __forceinline__ void mma16816h(float* c, const uint32_t* a,
                                          const uint32_t* b) {
    asm volatile("mma.sync.aligned.m16n8k16.row.col.f32.f16.f16.f32 "
        "{%0,%1,%2,%3}, {%4,%5,%6,%7}, {%8,%9}, {%0,%1,%2,%3};"
        : "+f"(c[0]), "+f"(c[1]), "+f"(c[2]), "+f"(c[3])
        : "r"(a[0]), "r"(a[1]), "r"(a[2]), "r"(a[3]), "r"(b[0]), "r"(b[1]));
}
__device__ __forceinline__ void ldmx4(uint32_t* r, uint32_t a) {
    asm volatile("ldmatrix.sync.aligned.m8n8.x4.shared.b16 {%0,%1,%2,%3}, [%4];"
        : "=r"(r[0]), "=r"(r[1]), "=r"(r[2]), "=r"(r[3]) : "r"(a));
}
__device__ __forceinline__ void ldmx4t(uint32_t* r, uint32_t a) {
    asm volatile("ldmatrix.sync.aligned.m8n8.x4.trans.shared.b16 {%0,%1,%2,%3}, [%4];"
        : "=r"(r[0]), "=r"(r[1]), "=r"(r[2]), "=r"(r[3]) : "r"(a));
}
__device__ __forceinline__ uint32_t packh(float v0, float v1) {
    fp16 h0 = __float2half_rn(v0), h1 = __float2half_rn(v1);
    return (uint32_t)__half_as_ushort(h0) | ((uint32_t)__half_as_ushort(h1) << 16);
}
__device__ __forceinline__ uint32_t bf_bits(float v) {
    bf16 h = __float2bfloat16_rn(v);
    return (uint32_t)(*reinterpret_cast<unsigned short*>(&h));
}
// fast exp on FMA/ALU pipes
__device__ __forceinline__ float fexp(float x) {
    x = fmaxf(x, -87.0f);
    float y = x * 1.44269504f;
    float fy = fmaf(x, 1.44269504f, 12582912.0f);
    float n = fy - 12582912.0f;
    float f = y - n;
    float p = 1.33335581e-3f;
    p = fmaf(p, f, 9.61812910e-3f);
    p = fmaf(p, f, 5.55041087e-2f);
    p = fmaf(p, f, 2.40226507e-1f);
    p = fmaf(p, f, 6.93147180e-1f);
    p = fmaf(p, f, 1.0f);
    uint32_t sc = (__float_as_uint(fy) + (127u - 0x400000u)) << 23;
    return __uint_as_float(sc) * p;
}

// ---------------- scratch (device globals; no allocations) ------------------
#define QKVW (3*Dc)      // 1536
__device__ float g_x[Bc*Tc*Dc];
__device__ float g_ksum[Bc*Hc*Tc];
__device__ uint32_t g_cnt[Bc*Tc*Tc];          // 4x packed byte counts
__device__ unsigned short g_mbf[Bc*Tc*Tc];    // bf16 mask (one-time pack)
__device__ fp16 g_h[Bc*Tc*Dc];
__device__ fp16 g_qkv[Bc*Tc*QKVW];
__device__ fp16 g_c[Bc*Tc*Dc];
__device__ fp16 g_f[Bc*Tc*Fc];
__device__ fp16 g_wqkvT[Lc*QKVW*Dc];
__device__ fp16 g_woT[Lc*Dc*Dc];
__device__ fp16 g_f1T[Lc*Dc*Fc];
__device__ fp16 g_f2T[Lc*Fc*Dc];

// ======================= weight transpose+convert (single fp16) ==============
__global__ void wconv_kernel(const float* __restrict__ W,
                             fp16* __restrict__ T, int K, int N, size_t ozstride)
{
    __shared__ float tile[32][33];
    const float* Wz = W + (size_t)blockIdx.z * K * N;
    fp16* Tz = T + (size_t)blockIdx.z * ozstride;
    int n0 = blockIdx.x * 32, k0 = blockIdx.y * 32;
    int tx = threadIdx.x, ty = threadIdx.y;
    #pragma unroll
    for (int i = 0; i < 4; i++)
        tile[ty + 8*i][tx] = Wz[(size_t)(k0 + ty + 8*i) * N + n0 + tx];
    __syncthreads();
    #pragma unroll
    for (int i = 0; i < 4; i++) {
        int n = n0 + ty + 8*i, k = k0 + tx;
        Tz[(size_t)n * K + k] = __float2half_rn(tile[tx][ty + 8*i]);
    }
}

// ======================= plain fp16 MMA GEMM =================================
#define STG 20480u
__global__ __launch_bounds__(256, 2) void gemm_mma(
    const fp16* __restrict__ A, const fp16* __restrict__ B,
    const float* __restrict__ bias, const float* __restrict__ resid,
    float* __restrict__ Cf, fp16* __restrict__ Ch,
    int M, int N, int K, int do_relu)
{
    extern __shared__ char smem[];
    uint32_t sb = smem_u32(smem);
    int t = threadIdx.x;
    int lane = t & 31, w = t >> 5;
    int row0 = blockIdx.y * 128, col0 = blockIdx.x * 128;
    int warpM = (w & 3) * 32, warpN = (w >> 2) * 64;
    int g = lane >> 2, tg = lane & 3;

    int arow = t >> 1, koff = (t & 1) * 16;
    const fp16* pA = A + (size_t)(row0 + arow) * K + koff;
    const fp16* pB = B + (size_t)(col0 + arow) * K + koff;
    uint32_t soff = (uint32_t)(arow * 80 + koff * 2);

    float c[2][8][4];
    #pragma unroll
    for (int i = 0; i < 2; i++)
        #pragma unroll
        for (int j = 0; j < 8; j++)
            #pragma unroll
            for (int r = 0; r < 4; r++) c[i][j][r] = 0.0f;

    int ns = K / 32;

    auto issue = [&](int kt) {
        uint32_t base = sb + (uint32_t)(kt & 1) * STG;
        const fp16* a;
        a = pA + kt * 32;
        cp16(base + soff, a);                 cp16(base + soff + 16, a + 8);
        a = pB + kt * 32;
        cp16(base + 10240 + soff, a);         cp16(base + 10240 + soff + 16, a + 8);
        asm volatile("cp.async.commit_group;" ::: "memory");
    };

    issue(0);
    for (int kt = 0; kt < ns; kt++) {
        if (kt + 1 < ns) {
            issue(kt + 1);
            asm volatile("cp.async.wait_group 1;" ::: "memory");
        } else {
            asm volatile("cp.async.wait_group 0;" ::: "memory");
        }
        __syncthreads();
        uint32_t base = sb + (uint32_t)(kt & 1) * STG;
        #pragma unroll
        for (int ks = 0; ks < 2; ks++) {
            int k0 = ks * 16;
            #pragma unroll
            for (int am = 0; am < 2; am++) {
                uint32_t aoff = (uint32_t)(
                    (warpM + am*16 + (lane & 15)) * 80
                    + (k0 + ((lane >> 4) << 3)) * 2);
                uint32_t ah[4];
                ldmx4(ah, base + aoff);
                #pragma unroll
                for (int n2 = 0; n2 < 4; n2++) {
                    uint32_t roff = (uint32_t)(
                        (warpN + n2*16 + (lane & 7) + (((lane >> 4) & 1) << 3)) * 80
                        + (k0 + (((lane >> 3) & 1) << 3)) * 2);
                    uint32_t kb[4];
                    ldmx4(kb, base + 10240 + roff);
                    uint32_t b0[2] = {kb[0], kb[1]}, b1[2] = {kb[2], kb[3]};
                    mma16816h(c[am][2*n2],   ah, b0);
                    mma16816h(c[am][2*n2+1], ah, b1);
                }
            }
        }
        __syncthreads();
    }

    #pragma unroll
    for (int am = 0; am < 2; am++) {
        #pragma unroll
        for (int bn = 0; bn < 8; bn++) {
            int n = col0 + warpN + (bn >> 1) * 16 + (bn & 1) * 8 + tg * 2;
            #pragma unroll
            for (int hf = 0; hf < 2; hf++) {
                int m = row0 + warpM + am*16 + g + hf*8;
                float v0 = c[am][bn][hf*2+0], v1 = c[am][bn][hf*2+1];
                if (bias) { v0 += bias[n]; v1 += bias[n+1]; }
                if (do_relu) { v0 = fmaxf(v0, 0.f); v1 = fmaxf(v1, 0.f); }
                if (resid) {
                    float2 r = *(const float2*)(resid + (size_t)m * N + n);
                    v0 += r.x; v1 += r.y;
                }
                if (Cf) *(float2*)(Cf + (size_t)m * N + n) = make_float2(v0, v1);
                if (Ch)
                    *(uint32_t*)(Ch + (size_t)m * N + n) = packh(v0, v1);
            }
        }
    }
}

// ======================= fused flash attention ==============================
// plain fp16; dense bias computed inline from packed counts + bf16 mask.
#define FS_Q     0u
#define FS_KS    18432u
#define FS_ST    20480u
#define FS_K     0u
#define FS_V     9216u
#define FS_STAGE 18432u
#define FS_TOTAL (20480u + 2u * 18432u)   // 57344

__global__ __launch_bounds__(256, 2) void flash_kernel(
    fp16* __restrict__ ch,
    const float* __restrict__ be_l, const float* __restrict__ bs_l)
{
    extern __shared__ char smem[];
    __shared__ float evtab[BIASDIM];
    uint32_t sb = smem_u32(smem);
    int t = threadIdx.x, lane = t & 31, w = t >> 5;
    int z = blockIdx.y, b = z >> 3, h = z & 7;
    int q0 = blockIdx.x * 128;
    size_t bT = (size_t)b * Tc;

    if (t < BIASDIM) {
        float s = 0.0f;
        #pragma unroll
        for (int a = 0; a < Ac; a++)
            s += be_l[t * Ac + a] * bs_l[a];
        evtab[t] = s;
    }
    {
        int row = t >> 1, half = t & 1;
        size_t gq = (bT + q0 + row) * QKVW + h * Ac + half * 32;
        uint32_t so = (uint32_t)(row * 144 + half * 64);
        #pragma unroll
        for (int c4 = 0; c4 < 4; c4++)
            cp16(sb + FS_Q + so + c4 * 16, g_qkv + gq + c4 * 8);
        if (t < 128)
            cp16(sb + FS_KS + t * 16, g_ksum + ((size_t)b * Hc + h) * Tc + t * 4);
    }
    auto issue = [&](int it) {
        uint32_t base = sb + FS_ST + (uint32_t)(it & 1) * FS_STAGE;
        #pragma unroll
        for (int j = 0; j < 2; j++) {
            int idx = t * 2 + j;
            int row = idx >> 3, c8 = idx & 7;
            size_t gk = (bT + it * 64 + row) * QKVW + Dc + h * Ac + c8 * 8;
            size_t gv = gk + Dc;
            uint32_t so = (uint32_t)(row * 144 + c8 * 16);
            cp16(base + FS_K + so, g_qkv + gk);
            cp16(base + FS_V + so, g_qkv + gv);
        }
        asm volatile("cp.async.commit_group;" ::: "memory");
    };
    issue(0);

    int wm = w * 16;
    int g = lane >> 2, tg = lane & 3;
    float m_[2] = {-1e30f, -1e30f};
    float l_[2] = {0.f, 0.f};
    float o[8][4] = {};

    for (int it = 0; it < 8; it++) {
        asm volatile("cp.async.wait_group 0;" ::: "memory");
        __syncthreads();
        if (it + 1 < 8) issue(it + 1);
        uint32_t stb = sb + FS_ST + (uint32_t)(it & 1) * FS_STAGE;

        // S = Q @ K^T over 64 k-cols
        float c[8][4] = {};
        #pragma unroll
        for (int s = 0; s < 4; s++) {
            uint32_t qoff = (uint32_t)((wm + (lane & 15)) * 144
                           + (s * 16 + ((lane >> 4) << 3)) * 2);
            uint32_t aq[4];
            ldmx4(aq, sb + FS_Q + qoff);
            #pragma unroll
            for (int n2 = 0; n2 < 4; n2++) {
                uint32_t koff = (uint32_t)(
                    (n2 * 16 + (lane & 7) + ((lane >> 4) << 3)) * 144
                    + (s * 16 + (((lane >> 3) & 1) << 3)) * 2);
                uint32_t kb[4];
                ldmx4(kb, stb + FS_K + koff);
                uint32_t b0[2] = {kb[0], kb[1]}, b1[2] = {kb[2], kb[3]};
                mma16816h(c[2*n2],   aq, b0);
                mma16816h(c[2*n2+1], aq, b1);
            }
        }
        // inline dense bias + scale + mask
        float e0 = evtab[0], e1 = evtab[1], e2 = evtab[2], e3 = evtab[3];
        #pragma unroll
        for (int nt = 0; nt < 8; nt++) {
            int kc = it * 64 + nt * 8 + tg * 2;
            float2 ks = *(float2*)(smem + FS_KS + kc * 4);
            #pragma unroll
            for (int hf = 0; hf < 2; hf++) {
                int row = q0 + wm + g + hf * 8;
                size_t off = (bT + row) * Tc + kc;
                uint2 cv = *(const uint2*)(g_cnt + off);
                uint32_t mk2 = *(const uint32_t*)(g_mbf + off);
                float d0 = e0 * (float)(cv.x & 255u)
                         + e1 * (float)((cv.x >> 8) & 255u)
                         + e2 * (float)((cv.x >> 16) & 255u)
                         + e3 * (float)(cv.x >> 24);
                float d1 = e0 * (float)(cv.y & 255u)
                         + e1 * (float)((cv.y >> 8) & 255u)
                         + e2 * (float)((cv.y >> 16) & 255u)
                         + e3 * (float)(cv.y >> 24);
                float m0 = __uint_as_float(mk2 << 16);
                float m1 = __uint_as_float(mk2 & 0xFFFF0000u);
                float v0 = (c[nt][hf*2+0] + d0 * ks.x) * 0.125f;
                float v1 = (c[nt][hf*2+1] + d1 * ks.y) * 0.125f;
                c[nt][hf*2+0] = v0 * m0 + (1.f - ceilf(m0)) * (-3.402823466e38f);
                c[nt][hf*2+1] = v1 * m1 + (1.f - ceilf(m1)) * (-3.402823466e38f);
            }
        }
        float scale[2];
        #pragma unroll
        for (int hf = 0; hf < 2; hf++) {
            float mx = -3.402823466e38f;
            #pragma unroll
            for (int nt = 0; nt < 8; nt++)
                mx = fmaxf(mx, fmaxf(c[nt][hf*2], c[nt][hf*2+1]));
            mx = fmaxf(mx, __shfl_xor_sync(0xffffffffu, mx, 1));
            mx = fmaxf(mx, __shfl_xor_sync(0xffffffffu, mx, 2));
            float mn = fmaxf(m_[hf], mx);
            scale[hf] = fexp(m_[hf] - mn);
            m_[hf] = mn;
            float sum = 0.f;
            #pragma unroll
            for (int nt = 0; nt < 8; nt++) {
                float p0 = fexp(c[nt][hf*2]   - mn);
                float p1 = fexp(c[nt][hf*2+1] - mn);
                c[nt][hf*2] = p0; c[nt][hf*2+1] = p1;
                sum += p0 + p1;
            }
            sum += __shfl_xor_sync(0xffffffffu, sum, 1);
            sum += __shfl_xor_sync(0xffffffffu, sum, 2);
            l_[hf] = l_[hf] * scale[hf] + sum;
        }
        #pragma unroll
        for (int ant = 0; ant < 8; ant++) {
            o[ant][0] *= scale[0]; o[ant][1] *= scale[0];
            o[ant][2] *= scale[1]; o[ant][3] *= scale[1];
        }
        // O += P @ V
        #pragma unroll
        for (int j = 0; j < 4; j++) {
            uint32_t ah[4];
            ah[0] = packh(c[2*j][0],   c[2*j][1]);
            ah[1] = packh(c[2*j][2],   c[2*j][3]);
            ah[2] = packh(c[2*j+1][0], c[2*j+1][1]);
            ah[3] = packh(c[2*j+1][2], c[2*j+1][3]);
            #pragma unroll
            for (int ap = 0; ap < 4; ap++) {
                uint32_t voff = (uint32_t)(
                    (j * 16 + (lane & 7) + (((lane >> 3) & 1) << 3)) * 144
                    + (ap * 16 + ((lane >> 4) << 3)) * 2);
                uint32_t vb[4];
                ldmx4t(vb, stb + FS_V + voff);
                uint32_t vh0[2] = {vb[0], vb[1]}, vh1[2] = {vb[2], vb[3]};
                mma16816h(o[2*ap],   ah, vh0);
                mma16816h(o[2*ap+1], ah, vh1);
            }
        }
    }
    #pragma unroll
    for (int hf = 0; hf < 2; hf++) {
        float inv = (l_[hf] > 0.f) ? 1.f / l_[hf] : 0.f;
        int row = q0 + wm + g + hf * 8;
        size_t base = (bT + row) * Dc + h * Ac + tg * 2;
        #pragma unroll
        for (int ant = 0; ant < 8; ant++) {
            float o0 = o[ant][hf*2+0] * inv, o1 = o[ant][hf*2+1] * inv;
            *(uint32_t*)(ch + base + ant * 8) = packh(o0, o1);
        }
    }
}

// ---------------- embedding + positional encoding ---------------------------
__global__ __launch_bounds__(512) void embed_pe_kernel(
    const int* __restrict__ tokens, const float* __restrict__ embed)
{
    int bt = blockIdx.x;
    int d  = threadIdx.x;
    int t  = bt % Tc;
    int tok = tokens[bt];
    float val = embed[(size_t)tok * Dc + d] * 22.62741699796952f;
    float expo  = (2.0f * (float)(d >> 1)) / (float)Dc;
    float denom = __powf(10000.0f, expo);
    float angle = (float)t / denom;
    val += ((d & 1) == 0) ? sinf(angle) : cosf(angle);
    g_x[(size_t)bt * Dc + d] = val;
}

// ---------------- layernorm: warp-per-token, fp16 out ------------------------
__global__ __launch_bounds__(256) void layernorm_kernel(
    const float* __restrict__ in, const float* __restrict__ gamma,
    const float* __restrict__ beta, float* __restrict__ outf,
    fp16* __restrict__ oh)
{
    int w = threadIdx.x >> 5, lane = threadIdx.x & 31;
    int token = blockIdx.x * 8 + w;
    size_t base = (size_t)token * Dc;

    float4 v[4];
    #pragma unroll
    for (int i = 0; i < 4; i++)
        v[i] = *(const float4*)(in + base + lane * 4 + i * 128);

    float s = 0.f;
    #pragma unroll
    for (int i = 0; i < 4; i++) s += v[i].x + v[i].y + v[i].z + v[i].w;
    #pragma unroll
    for (int off = 16; off > 0; off >>= 1)
        s += __shfl_xor_sync(0xffffffffu, s, off);
    float mu = s * (1.0f / Dc);

    float q = 0.f;
    #pragma unroll
    for (int i = 0; i < 4; i++) {
        float d0 = v[i].x - mu, d1 = v[i].y - mu;
        float d2 = v[i].z - mu, d3 = v[i].w - mu;
        q += d0*d0 + d1*d1 + d2*d2 + d3*d3;
    }
    #pragma unroll
    for (int off = 16; off > 0; off >>= 1)
        q += __shfl_xor_sync(0xffffffffu, q, off);
    float rstd = rsqrtf(q * (1.0f / Dc) + 1e-3f);

    #pragma unroll
    for (int i = 0; i < 4; i++) {
        int col = lane * 4 + i * 128;
        float4 gm = *(const float4*)(gamma + col);
        float4 bt = *(const float4*)(beta + col);
        float o0 = (v[i].x - mu) * rstd * gm.x + bt.x;
        float o1 = (v[i].y - mu) * rstd * gm.y + bt.y;
        float o2 = (v[i].z - mu) * rstd * gm.z + bt.z;
        float o3 = (v[i].w - mu) * rstd * gm.w + bt.w;
        if (outf)
            *(float4*)(outf + base + col) = make_float4(o0, o1, o2, o3);
        if (oh) {
            uint2 hv = make_uint2(packh(o0, o1), packh(o2, o3));
            *(uint2*)(oh + base + col) = hv;
        }
    }
}

// ---------------- ksum[b,h,t] ------------------------------------------------
__global__ __launch_bounds__(256) void ksum_kernel(void)
{
    int i = blockIdx.x * blockDim.x + threadIdx.x;
    if (i >= Bc * Tc * Hc) return;
    int bt = i >> 3, h = i & 7;
    int b = bt / Tc, tt = bt % Tc;
    const __half2* ph = (const __half2*)(g_qkv + (size_t)bt * QKVW + Dc + h * Ac);
    float s = 0.0f;
    #pragma unroll
    for (int j = 0; j < 32; j++) {
        float2 f2 = __half22float2(ph[j]);
        s += f2.x + f2.y;
    }
    g_ksum[((size_t)b * Hc + h) * Tc + tt] = s;
}

// ---------------- zero -------------------------------------------------------
__global__ __launch_bounds__(256) void zero_kernel(float* __restrict__ p, int n4)
{
    int i = blockIdx.x * blockDim.x + threadIdx.x;
    if (i < n4) ((float4*)p)[i] = make_float4(0.f, 0.f, 0.f, 0.f);
}

// ---------------- once: sparse edge COUNT scatter ----------------------------
__global__ __launch_bounds__(256) void cnt_scatter_kernel(
    const int* __restrict__ ab)
{
    int e = blockIdx.x * blockDim.x + threadIdx.x;
    if (e >= Ec) return;
    int ty = ab[e * 4 + 0];
    int b  = ab[e * 4 + 1];
    int q  = ab[e * 4 + 2];
    int k  = ab[e * 4 + 3];
    atomicAdd(&g_cnt[((size_t)b * Tc + q) * Tc + k], 1u << (ty * 8));
}

// ---------------- once: pack mask to bf16 ------------------------------------
__global__ __launch_bounds__(256) void mpack_kernel(const float* __restrict__ masks)
{
    int i = blockIdx.x * blockDim.x + threadIdx.x;
    if (i >= Bc * Tc * Tc / 4) return;
    float4 m = ((const float4*)masks)[i];
    uint2 o;
    o.x = bf_bits(m.x) | (bf_bits(m.y) << 16);
    o.y = bf_bits(m.z) | (bf_bits(m.w) << 16);
    ((uint2*)g_mbf)[i] = o;
}

// ---------------- host driver -----------------------------------------------
extern "C" void kernel_launch(void* const* d_in, const int* in_sizes, int n_in,
                              void* d_out, int out_size)
{
    const int*   tokens = (const int*)  d_in[0];
    const float* masks  = (const float*)d_in[1];
    const int*   ab     = (const int*)  d_in[2];
    const float* embed  = (const float*)d_in[3];
    const float* Wq     = (const float*)d_in[4];
    const float* Wk     = (const float*)d_in[5];
    const float* Wv     = (const float*)d_in[6];
    const float* Wo     = (const float*)d_in[7];
    const float* be     = (const float*)d_in[8];
    const float* bs     = (const float*)d_in[9];
    const float* ln_g   = (const float*)d_in[10];
    const float* ln_b   = (const float*)d_in[11];
    const float* ff1w   = (const float*)d_in[12];
    const float* ff1b   = (const float*)d_in[13];
    const float* ff2w   = (const float*)d_in[14];
    const float* ff2b   = (const float*)d_in[15];
    const float* lng    = (const float*)d_in[16];
    const float* lnb    = (const float*)d_in[17];
    float* out = (float*)d_out;

    float *x;
    uint32_t *cnt;
    fp16 *h, *qkv, *c, *f;
    fp16 *wqkvT, *woT, *f1T, *f2T;
    cudaGetSymbolAddress((void**)&x,     g_x);
    cudaGetSymbolAddress((void**)&cnt,   g_cnt);
    cudaGetSymbolAddress((void**)&h,     g_h);
    cudaGetSymbolAddress((void**)&qkv,   g_qkv);
    cudaGetSymbolAddress((void**)&c,     g_c);
    cudaGetSymbolAddress((void**)&f,     g_f);
    cudaGetSymbolAddress((void**)&wqkvT, g_wqkvT);
    cudaGetSymbolAddress((void**)&woT,   g_woT);
    cudaGetSymbolAddress((void**)&f1T,   g_f1T);
    cudaGetSymbolAddress((void**)&f2T,   g_f2T);

    cudaFuncSetAttribute(gemm_mma, cudaFuncAttributeMaxDynamicSharedMemorySize,
                         2 * STG);
    cudaFuncSetAttribute(flash_kernel, cudaFuncAttributeMaxDynamicSharedMemorySize,
                         FS_TOTAL);

    const int MT = Bc * Tc;                 // 8192 tokens
    dim3 wb(32, 8);

    wconv_kernel<<<dim3(16, 16, Lc), wb>>>(Wq, wqkvT,           Dc, Dc, (size_t)QKVW*Dc);
    wconv_kernel<<<dim3(16, 16, Lc), wb>>>(Wk, wqkvT + Dc*Dc,   Dc, Dc, (size_t)QKVW*Dc);
    wconv_kernel<<<dim3(16, 16, Lc), wb>>>(Wv, wqkvT + 2*Dc*Dc, Dc, Dc, (size_t)QKVW*Dc);
    wconv_kernel<<<dim3(16, 16, Lc), wb>>>(Wo,   woT, Dc, Dc, (size_t)Dc*Dc);
    wconv_kernel<<<dim3(64, 16, Lc), wb>>>(ff1w, f1T, Dc, Fc, (size_t)Dc*Fc);
    wconv_kernel<<<dim3(16, 64, Lc), wb>>>(ff2w, f2T, Fc, Dc, (size_t)Fc*Dc);

    // once per launch: counts + bf16 mask
    zero_kernel<<<(Bc*Tc*Tc/4 + 255)/256, 256>>>((float*)cnt, Bc*Tc*Tc/4);
    cnt_scatter_kernel<<<(Ec + 255)/256, 256>>>(ab);
    mpack_kernel<<<(Bc*Tc*Tc/4 + 255)/256, 256>>>(masks);

    embed_pe_kernel<<<MT, 512>>>(tokens, embed);

    for (int l = 0; l < Lc; l++) {
        size_t wqkv_ = (size_t)l * QKVW * Dc;
        size_t wo1  = (size_t)l * Dc * Dc;
        size_t wf1  = (size_t)l * Dc * Fc;
        size_t wf2  = (size_t)l * Fc * Dc;
        const float* be_l  = be + (size_t)l * BIASDIM * Ac;
        const float* bs_l  = bs + (size_t)l * Ac;
        const float* ln1g  = ln_g + (size_t)l * 2 * Dc;
        const float* ln1b  = ln_b + (size_t)l * 2 * Dc;
        const float* ln2g  = ln1g + Dc;
        const float* ln2b  = ln1b + Dc;
        const float* f1b   = ff1b + (size_t)l * Fc;
        const float* f2b   = ff2b + (size_t)l * Dc;

        layernorm_kernel<<<MT/8, 256>>>(x, ln1g, ln1b, nullptr, h);

        gemm_mma<<<dim3(QKVW/128, MT/128), 256, 2*STG>>>(h,
            wqkvT + wqkv_, nullptr, nullptr, nullptr, qkv, MT, QKVW, Dc, 0);

        ksum_kernel<<<(Bc*Tc*Hc + 255)/256, 256>>>();

        flash_kernel<<<dim3(Tc/128, Bc*Hc), 256, FS_TOTAL>>>(c, be_l, bs_l);

        gemm_mma<<<dim3(Dc/128, MT/128), 256, 2*STG>>>(c, woT+wo1,
            nullptr, x, x, nullptr, MT, Dc, Dc, 0);

        layernorm_kernel<<<MT/8, 256>>>(x, ln2g, ln2b, nullptr, h);
        gemm_mma<<<dim3(Fc/128, MT/128), 256, 2*STG>>>(h, f1T+wf1,
            f1b, nullptr, nullptr, f, MT, Fc, Dc, 1);
        gemm_mma<<<dim3(Dc/128, MT/128), 256, 2*STG>>>(f, f2T+wf2,
            f2b, x, x, nullptr, MT, Dc, Fc, 0);
    }

    layernorm_kernel<<<MT/8, 256>>>(x, lng, lnb, out, nullptr);
}

// round 17
// speedup vs baseline: 1.0901x; 1.0901x over previous
#include <cuda_runtime.h>
#include <cuda_fp16.h>
#include <cuda_bf16.h>
#include <math.h>
#include <stdint.h>

#define Lc 6
#define Bc 16
#define Tc 512
#define Dc 512
#define Hc 8
#define Ac 64
#define Fc 2048
#define Ec 200000
#define BIASDIM 4

typedef __half fp16;
typedef __nv_bfloat16 bf16;

// ======================= helpers =============================================
__device__ __forceinline__ uint32_t smem_u32(const void* p) {
    uint32_t a;
    asm("{ .reg .u64 t; cvta.to.shared.u64 t, %1; cvt.u32.u64 %0, t; }"
        : "=r"(a) : "l"(p));
    return a;
}
__device__ __forceinline__ void cp16(uint32_t s, const void* g) {
    asm volatile("cp.async.cg.shared.global [%0], [%1], 16;" :: "r"(s), "l"(g));
}
__device__ __forceinline__ void mma16816h(float* c, const uint32_t* a,
                                          const uint32_t* b) {
    asm volatile("mma.sync.aligned.m16n8k16.row.col.f32.f16.f16.f32 "
        "{%0,%1,%2,%3}, {%4,%5,%6,%7}, {%8,%9}, {%0,%1,%2,%3};"
        : "+f"(c[0]), "+f"(c[1]), "+f"(c[2]), "+f"(c[3])
        : "r"(a[0]), "r"(a[1]), "r"(a[2]), "r"(a[3]), "r"(b[0]), "r"(b[1]));
}
__device__ __forceinline__ void ldmx4(uint32_t* r, uint32_t a) {
    asm volatile("ldmatrix.sync.aligned.m8n8.x4.shared.b16 {%0,%1,%2,%3}, [%4];"
        : "=r"(r[0]), "=r"(r[1]), "=r"(r[2]), "=r"(r[3]) : "r"(a));
}
__device__ __forceinline__ void ldmx4t(uint32_t* r, uint32_t a) {
    asm volatile("ldmatrix.sync.aligned.m8n8.x4.trans.shared.b16 {%0,%1,%2,%3}, [%4];"
        : "=r"(r[0]), "=r"(r[1]), "=r"(r[2]), "=r"(r[3]) : "r"(a));
}
__device__ __forceinline__ uint32_t packh(float v0, float v1) {
    fp16 h0 = __float2half_rn(v0), h1 = __float2half_rn(v1);
    return (uint32_t)__half_as_ushort(h0) | ((uint32_t)__half_as_ushort(h1) << 16);
}
__device__ __forceinline__ uint32_t bf_bits(float v) {
    bf16 h = __float2bfloat16_rn(v);
    return (uint32_t)(*reinterpret_cast<unsigned short*>(&h));
}
__device__ __forceinline__ uint32_t pack_dm(float d, float m) {
    return bf_bits(d) | (bf_bits(m) << 16);
}
// fast exp on FMA/ALU pipes
__device__ __forceinline__ float fexp(float x) {
    x = fmaxf(x, -87.0f);
    float y = x * 1.44269504f;
    float fy = fmaf(x, 1.44269504f, 12582912.0f);
    float n = fy - 12582912.0f;
    float f = y - n;
    float p = 1.33335581e-3f;
    p = fmaf(p, f, 9.61812910e-3f);
    p = fmaf(p, f, 5.55041087e-2f);
    p = fmaf(p, f, 2.40226507e-1f);
    p = fmaf(p, f, 6.93147180e-1f);
    p = fmaf(p, f, 1.0f);
    uint32_t sc = (__float_as_uint(fy) + (127u - 0x400000u)) << 23;
    return __uint_as_float(sc) * p;
}

// ---------------- scratch (device globals; no allocations) ------------------
#define QKVW (3*Dc)      // 1536
__device__ float g_x[Bc*Tc*Dc];
__device__ float g_ksum[Bc*Hc*Tc];
__device__ uint32_t g_cnt[Bc*Tc*Tc];
__device__ uint32_t g_cmb[Bc*Tc*Tc];          // {bf16 mask <<16 | bf16 dense}
__device__ fp16 g_h[Bc*Tc*Dc];
__device__ fp16 g_qkv[Bc*Tc*QKVW];
__device__ fp16 g_c[Bc*Tc*Dc];
__device__ fp16 g_f[Bc*Tc*Fc];
__device__ fp16 g_wqkvT[Lc*QKVW*Dc];
__device__ fp16 g_woT[Lc*Dc*Dc];
__device__ fp16 g_f1T[Lc*Dc*Fc];
__device__ fp16 g_f2T[Lc*Fc*Dc];

// ======================= weight transpose+convert (single fp16) ==============
__global__ void wconv_kernel(const float* __restrict__ W,
                             fp16* __restrict__ T, int K, int N, size_t ozstride)
{
    __shared__ float tile[32][33];
    const float* Wz = W + (size_t)blockIdx.z * K * N;
    fp16* Tz = T + (size_t)blockIdx.z * ozstride;
    int n0 = blockIdx.x * 32, k0 = blockIdx.y * 32;
    int tx = threadIdx.x, ty = threadIdx.y;
    #pragma unroll
    for (int i = 0; i < 4; i++)
        tile[ty + 8*i][tx] = Wz[(size_t)(k0 + ty + 8*i) * N + n0 + tx];
    __syncthreads();
    #pragma unroll
    for (int i = 0; i < 4; i++) {
        int n = n0 + ty + 8*i, k = k0 + tx;
        Tz[(size_t)n * K + k] = __float2half_rn(tile[tx][ty + 8*i]);
    }
}

// ======================= plain fp16 MMA GEMM (3-stage pipeline) ==============
#define STG 20480u
__global__ __launch_bounds__(256, 2) void gemm_mma(
    const fp16* __restrict__ A, const fp16* __restrict__ B,
    const float* __restrict__ bias, const float* __restrict__ resid,
    float* __restrict__ Cf, fp16* __restrict__ Ch,
    int M, int N, int K, int do_relu)
{
    extern __shared__ char smem[];
    uint32_t sb = smem_u32(smem);
    int t = threadIdx.x;
    int lane = t & 31, w = t >> 5;
    int row0 = blockIdx.y * 128, col0 = blockIdx.x * 128;
    int warpM = (w & 3) * 32, warpN = (w >> 2) * 64;
    int g = lane >> 2, tg = lane & 3;

    int arow = t >> 1, koff = (t & 1) * 16;
    const fp16* pA = A + (size_t)(row0 + arow) * K + koff;
    const fp16* pB = B + (size_t)(col0 + arow) * K + koff;
    uint32_t soff = (uint32_t)(arow * 80 + koff * 2);

    float c[2][8][4];
    #pragma unroll
    for (int i = 0; i < 2; i++)
        #pragma unroll
        for (int j = 0; j < 8; j++)
            #pragma unroll
            for (int r = 0; r < 4; r++) c[i][j][r] = 0.0f;

    int ns = K / 32;

    auto issue = [&](int kt) {
        uint32_t base = sb + (uint32_t)(kt % 3) * STG;
        const fp16* a;
        a = pA + kt * 32;
        cp16(base + soff, a);                 cp16(base + soff + 16, a + 8);
        a = pB + kt * 32;
        cp16(base + 10240 + soff, a);         cp16(base + 10240 + soff + 16, a + 8);
        asm volatile("cp.async.commit_group;" ::: "memory");
    };

    issue(0);
    issue(1);
    for (int kt = 0; kt < ns; kt++) {
        if (kt + 1 < ns) {
            asm volatile("cp.async.wait_group 1;" ::: "memory");
        } else {
            asm volatile("cp.async.wait_group 0;" ::: "memory");
        }
        __syncthreads();
        if (kt + 2 < ns) issue(kt + 2);
        uint32_t base = sb + (uint32_t)(kt % 3) * STG;
        #pragma unroll
        for (int ks = 0; ks < 2; ks++) {
            int k0 = ks * 16;
            #pragma unroll
            for (int am = 0; am < 2; am++) {
                uint32_t aoff = (uint32_t)(
                    (warpM + am*16 + (lane & 15)) * 80
                    + (k0 + ((lane >> 4) << 3)) * 2);
                uint32_t ah[4];
                ldmx4(ah, base + aoff);
                #pragma unroll
                for (int n2 = 0; n2 < 4; n2++) {
                    uint32_t roff = (uint32_t)(
                        (warpN + n2*16 + (lane & 7) + (((lane >> 4) & 1) << 3)) * 80
                        + (k0 + (((lane >> 3) & 1) << 3)) * 2);
                    uint32_t kb[4];
                    ldmx4(kb, base + 10240 + roff);
                    uint32_t b0[2] = {kb[0], kb[1]}, b1[2] = {kb[2], kb[3]};
                    mma16816h(c[am][2*n2],   ah, b0);
                    mma16816h(c[am][2*n2+1], ah, b1);
                }
            }
        }
    }

    __syncthreads();
    #pragma unroll
    for (int am = 0; am < 2; am++) {
        #pragma unroll
        for (int bn = 0; bn < 8; bn++) {
            int n = col0 + warpN + (bn >> 1) * 16 + (bn & 1) * 8 + tg * 2;
            #pragma unroll
            for (int hf = 0; hf < 2; hf++) {
                int m = row0 + warpM + am*16 + g + hf*8;
                float v0 = c[am][bn][hf*2+0], v1 = c[am][bn][hf*2+1];
                if (bias) { v0 += bias[n]; v1 += bias[n+1]; }
                if (do_relu) { v0 = fmaxf(v0, 0.f); v1 = fmaxf(v1, 0.f); }
                if (resid) {
                    float2 r = *(const float2*)(resid + (size_t)m * N + n);
                    v0 += r.x; v1 += r.y;
                }
                if (Cf) *(float2*)(Cf + (size_t)m * N + n) = make_float2(v0, v1);
                if (Ch)
                    *(uint32_t*)(Ch + (size_t)m * N + n) = packh(v0, v1);
            }
        }
    }
}

// ======================= fused flash attention (plain fp16) ==================
#define FS_Q     0u
#define FS_KS    18432u
#define FS_ST    20480u
#define FS_K     0u
#define FS_V     9216u
#define FS_STAGE 18432u
#define FS_TOTAL (20480u + 2u * 18432u)   // 57344

__global__ __launch_bounds__(256, 2) void flash_kernel(fp16* __restrict__ ch)
{
    extern __shared__ char smem[];
    uint32_t sb = smem_u32(smem);
    int t = threadIdx.x, lane = t & 31, w = t >> 5;
    int z = blockIdx.y, b = z >> 3, h = z & 7;
    int q0 = blockIdx.x * 128;
    size_t bT = (size_t)b * Tc;

    {
        int row = t >> 1, half = t & 1;
        size_t gq = (bT + q0 + row) * QKVW + h * Ac + half * 32;
        uint32_t so = (uint32_t)(row * 144 + half * 64);
        #pragma unroll
        for (int c4 = 0; c4 < 4; c4++)
            cp16(sb + FS_Q + so + c4 * 16, g_qkv + gq + c4 * 8);
        if (t < 128)
            cp16(sb + FS_KS + t * 16, g_ksum + ((size_t)b * Hc + h) * Tc + t * 4);
    }
    auto issue = [&](int it) {
        uint32_t base = sb + FS_ST + (uint32_t)(it & 1) * FS_STAGE;
        #pragma unroll
        for (int j = 0; j < 2; j++) {
            int idx = t * 2 + j;
            int row = idx >> 3, c8 = idx & 7;
            size_t gk = (bT + it * 64 + row) * QKVW + Dc + h * Ac + c8 * 8;
            size_t gv = gk + Dc;
            uint32_t so = (uint32_t)(row * 144 + c8 * 16);
            cp16(base + FS_K + so, g_qkv + gk);
            cp16(base + FS_V + so, g_qkv + gv);
        }
        asm volatile("cp.async.commit_group;" ::: "memory");
    };
    issue(0);

    int wm = w * 16;
    int g = lane >> 2, tg = lane & 3;
    float m_[2] = {-1e30f, -1e30f};
    float l_[2] = {0.f, 0.f};
    float o[8][4] = {};

    for (int it = 0; it < 8; it++) {
        asm volatile("cp.async.wait_group 0;" ::: "memory");
        __syncthreads();
        if (it + 1 < 8) issue(it + 1);
        uint32_t stb = sb + FS_ST + (uint32_t)(it & 1) * FS_STAGE;

        // S = Q @ K^T over 64 k-cols
        float c[8][4] = {};
        #pragma unroll
        for (int s = 0; s < 4; s++) {
            uint32_t qoff = (uint32_t)((wm + (lane & 15)) * 144
                           + (s * 16 + ((lane >> 4) << 3)) * 2);
            uint32_t aq[4];
            ldmx4(aq, sb + FS_Q + qoff);
            #pragma unroll
            for (int n2 = 0; n2 < 4; n2++) {
                uint32_t koff = (uint32_t)(
                    (n2 * 16 + (lane & 7) + ((lane >> 4) << 3)) * 144
                    + (s * 16 + (((lane >> 3) & 1) << 3)) * 2);
                uint32_t kb[4];
                ldmx4(kb, stb + FS_K + koff);
                uint32_t b0[2] = {kb[0], kb[1]}, b1[2] = {kb[2], kb[3]};
                mma16816h(c[2*n2],   aq, b0);
                mma16816h(c[2*n2+1], aq, b1);
            }
        }
        #pragma unroll
        for (int nt = 0; nt < 8; nt++) {
            int kc = it * 64 + nt * 8 + tg * 2;
            float2 ks = *(float2*)(smem + FS_KS + kc * 4);
            #pragma unroll
            for (int hf = 0; hf < 2; hf++) {
                int row = q0 + wm + g + hf * 8;
                size_t off = (bT + row) * Tc + kc;
                uint2 dm = *(const uint2*)(g_cmb + off);
                float d0 = __uint_as_float(dm.x << 16);
                float m0 = __uint_as_float(dm.x & 0xFFFF0000u);
                float d1 = __uint_as_float(dm.y << 16);
                float m1 = __uint_as_float(dm.y & 0xFFFF0000u);
                float v0 = (c[nt][hf*2+0] + d0 * ks.x) * 0.125f;
                float v1 = (c[nt][hf*2+1] + d1 * ks.y) * 0.125f;
                c[nt][hf*2+0] = v0 * m0 + (1.f - ceilf(m0)) * (-3.402823466e38f);
                c[nt][hf*2+1] = v1 * m1 + (1.f - ceilf(m1)) * (-3.402823466e38f);
            }
        }
        float scale[2];
        #pragma unroll
        for (int hf = 0; hf < 2; hf++) {
            float mx = -3.402823466e38f;
            #pragma unroll
            for (int nt = 0; nt < 8; nt++)
                mx = fmaxf(mx, fmaxf(c[nt][hf*2], c[nt][hf*2+1]));
            mx = fmaxf(mx, __shfl_xor_sync(0xffffffffu, mx, 1));
            mx = fmaxf(mx, __shfl_xor_sync(0xffffffffu, mx, 2));
            float mn = fmaxf(m_[hf], mx);
            scale[hf] = fexp(m_[hf] - mn);
            m_[hf] = mn;
            float sum = 0.f;
            #pragma unroll
            for (int nt = 0; nt < 8; nt++) {
                float p0 = fexp(c[nt][hf*2]   - mn);
                float p1 = fexp(c[nt][hf*2+1] - mn);
                c[nt][hf*2] = p0; c[nt][hf*2+1] = p1;
                sum += p0 + p1;
            }
            sum += __shfl_xor_sync(0xffffffffu, sum, 1);
            sum += __shfl_xor_sync(0xffffffffu, sum, 2);
            l_[hf] = l_[hf] * scale[hf] + sum;
        }
        #pragma unroll
        for (int ant = 0; ant < 8; ant++) {
            o[ant][0] *= scale[0]; o[ant][1] *= scale[0];
            o[ant][2] *= scale[1]; o[ant][3] *= scale[1];
        }
        // O += P @ V
        #pragma unroll
        for (int j = 0; j < 4; j++) {
            uint32_t ah[4];
            ah[0] = packh(c[2*j][0],   c[2*j][1]);
            ah[1] = packh(c[2*j][2],   c[2*j][3]);
            ah[2] = packh(c[2*j+1][0], c[2*j+1][1]);
            ah[3] = packh(c[2*j+1][2], c[2*j+1][3]);
            #pragma unroll
            for (int ap = 0; ap < 4; ap++) {
                uint32_t voff = (uint32_t)(
                    (j * 16 + (lane & 7) + (((lane >> 3) & 1) << 3)) * 144
                    + (ap * 16 + ((lane >> 4) << 3)) * 2);
                uint32_t vb[4];
                ldmx4t(vb, stb + FS_V + voff);
                uint32_t vh0[2] = {vb[0], vb[1]}, vh1[2] = {vb[2], vb[3]};
                mma16816h(o[2*ap],   ah, vh0);
                mma16816h(o[2*ap+1], ah, vh1);
            }
        }
    }
    #pragma unroll
    for (int hf = 0; hf < 2; hf++) {
        float inv = (l_[hf] > 0.f) ? 1.f / l_[hf] : 0.f;
        int row = q0 + wm + g + hf * 8;
        size_t base = (bT + row) * Dc + h * Ac + tg * 2;
        #pragma unroll
        for (int ant = 0; ant < 8; ant++) {
            float o0 = o[ant][hf*2+0] * inv, o1 = o[ant][hf*2+1] * inv;
            *(uint32_t*)(ch + base + ant * 8) = packh(o0, o1);
        }
    }
}

// ---------------- embedding + positional encoding ---------------------------
__global__ __launch_bounds__(512) void embed_pe_kernel(
    const int* __restrict__ tokens, const float* __restrict__ embed)
{
    int bt = blockIdx.x;
    int d  = threadIdx.x;
    int t  = bt % Tc;
    int tok = tokens[bt];
    float val = embed[(size_t)tok * Dc + d] * 22.62741699796952f;
    float expo  = (2.0f * (float)(d >> 1)) / (float)Dc;
    float denom = __powf(10000.0f, expo);
    float angle = (float)t / denom;
    val += ((d & 1) == 0) ? sinf(angle) : cosf(angle);
    g_x[(size_t)bt * Dc + d] = val;
}

// ---------------- layernorm: warp-per-token, fp16 out ------------------------
__global__ __launch_bounds__(256) void layernorm_kernel(
    const float* __restrict__ in, const float* __restrict__ gamma,
    const float* __restrict__ beta, float* __restrict__ outf,
    fp16* __restrict__ oh)
{
    int w = threadIdx.x >> 5, lane = threadIdx.x & 31;
    int token = blockIdx.x * 8 + w;
    size_t base = (size_t)token * Dc;

    float4 v[4];
    #pragma unroll
    for (int i = 0; i < 4; i++)
        v[i] = *(const float4*)(in + base + lane * 4 + i * 128);

    float s = 0.f;
    #pragma unroll
    for (int i = 0; i < 4; i++) s += v[i].x + v[i].y + v[i].z + v[i].w;
    #pragma unroll
    for (int off = 16; off > 0; off >>= 1)
        s += __shfl_xor_sync(0xffffffffu, s, off);
    float mu = s * (1.0f / Dc);

    float q = 0.f;
    #pragma unroll
    for (int i = 0; i < 4; i++) {
        float d0 = v[i].x - mu, d1 = v[i].y - mu;
        float d2 = v[i].z - mu, d3 = v[i].w - mu;
        q += d0*d0 + d1*d1 + d2*d2 + d3*d3;
    }
    #pragma unroll
    for (int off = 16; off > 0; off >>= 1)
        q += __shfl_xor_sync(0xffffffffu, q, off);
    float rstd = rsqrtf(q * (1.0f / Dc) + 1e-3f);

    #pragma unroll
    for (int i = 0; i < 4; i++) {
        int col = lane * 4 + i * 128;
        float4 gm = *(const float4*)(gamma + col);
        float4 bt = *(const float4*)(beta + col);
        float o0 = (v[i].x - mu) * rstd * gm.x + bt.x;
        float o1 = (v[i].y - mu) * rstd * gm.y + bt.y;
        float o2 = (v[i].z - mu) * rstd * gm.z + bt.z;
        float o3 = (v[i].w - mu) * rstd * gm.w + bt.w;
        if (outf)
            *(float4*)(outf + base + col) = make_float4(o0, o1, o2, o3);
        if (oh) {
            uint2 hv = make_uint2(packh(o0, o1), packh(o2, o3));
            *(uint2*)(oh + base + col) = hv;
        }
    }
}

// ---------------- ksum[b,h,t] ------------------------------------------------
__global__ __launch_bounds__(256) void ksum_kernel(void)
{
    int i = blockIdx.x * blockDim.x + threadIdx.x;
    if (i >= Bc * Tc * Hc) return;
    int bt = i >> 3, h = i & 7;
    int b = bt / Tc, tt = bt % Tc;
    const __half2* ph = (const __half2*)(g_qkv + (size_t)bt * QKVW + Dc + h * Ac);
    float s = 0.0f;
    #pragma unroll
    for (int j = 0; j < 32; j++) {
        float2 f2 = __half22float2(ph[j]);
        s += f2.x + f2.y;
    }
    g_ksum[((size_t)b * Hc + h) * Tc + tt] = s;
}

// ---------------- zero -------------------------------------------------------
__global__ __launch_bounds__(256) void zero_kernel(float* __restrict__ p, int n4)
{
    int i = blockIdx.x * blockDim.x + threadIdx.x;
    if (i < n4) ((float4*)p)[i] = make_float4(0.f, 0.f, 0.f, 0.f);
}

// ---------------- once: sparse edge COUNT scatter ----------------------------
__global__ __launch_bounds__(256) void cnt_scatter_kernel(
    const int* __restrict__ ab)
{
    int e = blockIdx.x * blockDim.x + threadIdx.x;
    if (e >= Ec) return;
    int ty = ab[e * 4 + 0];
    int b  = ab[e * 4 + 1];
    int q  = ab[e * 4 + 2];
    int k  = ab[e * 4 + 3];
    atomicAdd(&g_cnt[((size_t)b * Tc + q) * Tc + k], 1u << (ty * 8));
}

// ---------------- per-layer combo: dense from counts + mask ------------------
__global__ __launch_bounds__(256) void cmb2_kernel(
    const float* __restrict__ masks, const float* __restrict__ be_l,
    const float* __restrict__ bs_l)
{
    __shared__ float evtab[BIASDIM];
    if (threadIdx.x < BIASDIM) {
        float s = 0.0f;
        #pragma unroll
        for (int a = 0; a < Ac; a++)
            s += be_l[threadIdx.x * Ac + a] * bs_l[a];
        evtab[threadIdx.x] = s;
    }
    __syncthreads();
    float e0 = evtab[0], e1 = evtab[1], e2 = evtab[2], e3 = evtab[3];
    int i = blockIdx.x * blockDim.x + threadIdx.x;
    if (i >= Bc * Tc * Tc / 4) return;
    uint4 cv = ((const uint4*)g_cnt)[i];
    float4 mk = ((const float4*)masks)[i];
    uint32_t cs[4] = {cv.x, cv.y, cv.z, cv.w};
    float ms[4] = {mk.x, mk.y, mk.z, mk.w};
    uint4 o;
    uint32_t* op = (uint32_t*)&o;
    #pragma unroll
    for (int j = 0; j < 4; j++) {
        uint32_t cc = cs[j];
        float d = e0 * (float)(cc & 255u)
                + e1 * (float)((cc >> 8) & 255u)
                + e2 * (float)((cc >> 16) & 255u)
                + e3 * (float)(cc >> 24);
        op[j] = pack_dm(d, ms[j]);
    }
    ((uint4*)g_cmb)[i] = o;
}

// ---------------- host driver -----------------------------------------------
extern "C" void kernel_launch(void* const* d_in, const int* in_sizes, int n_in,
                              void* d_out, int out_size)
{
    const int*   tokens = (const int*)  d_in[0];
    const float* masks  = (const float*)d_in[1];
    const int*   ab     = (const int*)  d_in[2];
    const float* embed  = (const float*)d_in[3];
    const float* Wq     = (const float*)d_in[4];
    const float* Wk     = (const float*)d_in[5];
    const float* Wv     = (const float*)d_in[6];
    const float* Wo     = (const float*)d_in[7];
    const float* be     = (const float*)d_in[8];
    const float* bs     = (const float*)d_in[9];
    const float* ln_g   = (const float*)d_in[10];
    const float* ln_b   = (const float*)d_in[11];
    const float* ff1w   = (const float*)d_in[12];
    const float* ff1b   = (const float*)d_in[13];
    const float* ff2w   = (const float*)d_in[14];
    const float* ff2b   = (const float*)d_in[15];
    const float* lng    = (const float*)d_in[16];
    const float* lnb    = (const float*)d_in[17];
    float* out = (float*)d_out;

    float *x;
    uint32_t *cnt;
    fp16 *h, *qkv, *c, *f;
    fp16 *wqkvT, *woT, *f1T, *f2T;
    cudaGetSymbolAddress((void**)&x,     g_x);
    cudaGetSymbolAddress((void**)&cnt,   g_cnt);
    cudaGetSymbolAddress((void**)&h,     g_h);
    cudaGetSymbolAddress((void**)&qkv,   g_qkv);
    cudaGetSymbolAddress((void**)&c,     g_c);
    cudaGetSymbolAddress((void**)&f,     g_f);
    cudaGetSymbolAddress((void**)&wqkvT, g_wqkvT);
    cudaGetSymbolAddress((void**)&woT,   g_woT);
    cudaGetSymbolAddress((void**)&f1T,   g_f1T);
    cudaGetSymbolAddress((void**)&f2T,   g_f2T);

    cudaFuncSetAttribute(gemm_mma, cudaFuncAttributeMaxDynamicSharedMemorySize,
                         3 * STG);
    cudaFuncSetAttribute(flash_kernel, cudaFuncAttributeMaxDynamicSharedMemorySize,
                         FS_TOTAL);

    const int MT = Bc * Tc;                 // 8192 tokens
    dim3 wb(32, 8);

    wconv_kernel<<<dim3(16, 16, Lc), wb>>>(Wq, wqkvT,           Dc, Dc, (size_t)QKVW*Dc);
    wconv_kernel<<<dim3(16, 16, Lc), wb>>>(Wk, wqkvT + Dc*Dc,   Dc, Dc, (size_t)QKVW*Dc);
    wconv_kernel<<<dim3(16, 16, Lc), wb>>>(Wv, wqkvT + 2*Dc*Dc, Dc, Dc, (size_t)QKVW*Dc);
    wconv_kernel<<<dim3(16, 16, Lc), wb>>>(Wo,   woT, Dc, Dc, (size_t)Dc*Dc);
    wconv_kernel<<<dim3(64, 16, Lc), wb>>>(ff1w, f1T, Dc, Fc, (size_t)Dc*Fc);
    wconv_kernel<<<dim3(16, 64, Lc), wb>>>(ff2w, f2T, Fc, Dc, (size_t)Fc*Dc);

    zero_kernel<<<(Bc*Tc*Tc/4 + 255)/256, 256>>>((float*)cnt, Bc*Tc*Tc/4);
    cnt_scatter_kernel<<<(Ec + 255)/256, 256>>>(ab);

    embed_pe_kernel<<<MT, 512>>>(tokens, embed);

    for (int l = 0; l < Lc; l++) {
        size_t wqkv_ = (size_t)l * QKVW * Dc;
        size_t wo1  = (size_t)l * Dc * Dc;
        size_t wf1  = (size_t)l * Dc * Fc;
        size_t wf2  = (size_t)l * Fc * Dc;
        const float* be_l  = be + (size_t)l * BIASDIM * Ac;
        const float* bs_l  = bs + (size_t)l * Ac;
        const float* ln1g  = ln_g + (size_t)l * 2 * Dc;
        const float* ln1b  = ln_b + (size_t)l * 2 * Dc;
        const float* ln2g  = ln1g + Dc;
        const float* ln2b  = ln1b + Dc;
        const float* f1b   = ff1b + (size_t)l * Fc;
        const float* f2b   = ff2b + (size_t)l * Dc;

        layernorm_kernel<<<MT/8, 256>>>(x, ln1g, ln1b, nullptr, h);

        gemm_mma<<<dim3(QKVW/128, MT/128), 256, 3*STG>>>(h,
            wqkvT + wqkv_, nullptr, nullptr, nullptr, qkv, MT, QKVW, Dc, 0);

        ksum_kernel<<<(Bc*Tc*Hc + 255)/256, 256>>>();
        cmb2_kernel<<<(Bc*Tc*Tc/4 + 255)/256, 256>>>(masks, be_l, bs_l);

        flash_kernel<<<dim3(Tc/128, Bc*Hc), 256, FS_TOTAL>>>(c);

        gemm_mma<<<dim3(Dc/128, MT/128), 256, 3*STG>>>(c, woT+wo1,
            nullptr, x, x, nullptr, MT, Dc, Dc, 0);

        layernorm_kernel<<<MT/8, 256>>>(x, ln2g, ln2b, nullptr, h);
        gemm_mma<<<dim3(Fc/128, MT/128), 256, 3*STG>>>(h, f1T+wf1,
            f1b, nullptr, nullptr, f, MT, Fc, Dc, 1);
        gemm_mma<<<dim3(Dc/128, MT/128), 256, 3*STG>>>(f, f2T+wf2,
            f2b, x, x, nullptr, MT, Dc, Fc, 0);
    }

    layernorm_kernel<<<MT/8, 256>>>(x, lng, lnb, out, nullptr);
}